// round 14
// baseline (speedup 1.0000x reference)
#include <cuda_runtime.h>
#include <cuda_fp16.h>
#include <cstdint>

// MoE SwiGLU via fp16 tensor cores (mma.m16n8k16, fp32 accum), fused
// fp32->fp16 conversion in the smem load path. Weights stay fp32 in HBM.
// R13: BM 128->64 (4 token strips) to kill multinomial-tail waste; gemm2 at
// 3 CTAs/SM. Strip stays fastest grid dim -> concurrent same-weight blocks
// share L2 lines.
//   1) route_kernel : bucket 1024 (token,slot) pairs by expert
//   2) gemm1_kernel : hbuf(fp16) = silu(x.w1[e]^T) * (x.w3[e]^T)
//   3) gemm2_kernel : out = hbuf . w2[e]   (fp32 out)

namespace {
constexpr int kE = 8;
constexpr int kTOPK = 2;
constexpr int kH = 2816;
constexpr int kD = 1024;
constexpr int NP = 1024;

constexpr int NSTRIP = 4;               // token strips of 64

// GEMM1: BM=64 tokens, BN=64 h (x2 matrices), BK=32
constexpr int G1_NT_H = kH / 64;        // 44 h-tiles
constexpr int G1_XS = 40;               // smem row stride fp16 (32+8 pad) — proven
// GEMM2: BM=64 tokens, BN=64 d, BK=32
constexpr int G2_NT_D = kD / 64;        // 16 d-tiles
constexpr int G2_AS = 40;               // A row stride fp16 (32+8 pad)
constexpr int G2_BS = 72;               // B row stride fp16 (64+8 pad)
}

__device__ int    g_off[kE + 1];
__device__ int    g_pairs[NP];
__device__ __half g_hbuf[(size_t)NP * kH];   // 5.77 MB fp16 intermediate

// ---------------------------------------------------------------------------
// helpers
// ---------------------------------------------------------------------------
__device__ __forceinline__ uint32_t s2u(const void* p) {
    return (uint32_t)__cvta_generic_to_shared(p);
}
__device__ __forceinline__ void ldsm_x4(uint32_t r[4], uint32_t addr) {
    asm volatile("ldmatrix.sync.aligned.m8n8.x4.shared.b16 {%0,%1,%2,%3}, [%4];"
                 : "=r"(r[0]), "=r"(r[1]), "=r"(r[2]), "=r"(r[3]) : "r"(addr));
}
__device__ __forceinline__ void ldsm_x4_t(uint32_t r[4], uint32_t addr) {
    asm volatile("ldmatrix.sync.aligned.m8n8.x4.trans.shared.b16 {%0,%1,%2,%3}, [%4];"
                 : "=r"(r[0]), "=r"(r[1]), "=r"(r[2]), "=r"(r[3]) : "r"(addr));
}
__device__ __forceinline__ void mma16816(float c[4], const uint32_t a[4],
                                         uint32_t b0, uint32_t b1) {
    asm volatile(
        "mma.sync.aligned.m16n8k16.row.col.f32.f16.f16.f32 "
        "{%0,%1,%2,%3},{%4,%5,%6,%7},{%8,%9},{%0,%1,%2,%3};"
        : "+f"(c[0]), "+f"(c[1]), "+f"(c[2]), "+f"(c[3])
        : "r"(a[0]), "r"(a[1]), "r"(a[2]), "r"(a[3]), "r"(b0), "r"(b1));
}
__device__ __forceinline__ uint32_t h2u(__half2 h) {
    return *reinterpret_cast<uint32_t*>(&h);
}
__device__ __forceinline__ uint2 cvt4(float4 v) {
    uint2 u = { h2u(__floats2half2_rn(v.x, v.y)),
                h2u(__floats2half2_rn(v.z, v.w)) };
    return u;
}
__device__ __forceinline__ float silu(float z) {
    return z / (1.0f + __expf(-z));
}

// ---------------------------------------------------------------------------
// Routing (int32/int64 dtype auto-detect; validated R3+)
// ---------------------------------------------------------------------------
__global__ void route_kernel(const void* __restrict__ eidx_raw) {
    __shared__ int cnt[kE];
    __shared__ int cur[kE];
    __shared__ int not64;
    int tid = threadIdx.x;
    if (tid < kE) cnt[tid] = 0;
    if (tid == 0) not64 = 0;
    __syncthreads();

    const long long* p64 = (const long long*)eidx_raw;
    if (tid < NP / 2) {
        long long v = p64[tid];
        if (v < 0 || v >= kE) not64 = 1;
    }
    __syncthreads();

    int e = not64 ? ((const int*)eidx_raw)[tid] : (int)p64[tid];

    atomicAdd(&cnt[e], 1);
    __syncthreads();
    if (tid == 0) {
        int o = 0;
        for (int i = 0; i < kE; i++) { g_off[i] = o; cur[i] = o; o += cnt[i]; }
        g_off[kE] = o;
    }
    __syncthreads();
    int p = atomicAdd(&cur[e], 1);
    g_pairs[p] = tid;
}

// ---------------------------------------------------------------------------
// GEMM1 + SwiGLU. 256 threads, 8 warps: 2(m,32) x 4(n,16). 32 stages of k32.
// grid.x = 4 strips * 44 htiles * 8 experts = 1408.  2 CTAs/SM.
// Block tile: 64 tokens x 64 h for BOTH w1 and w3.
// ---------------------------------------------------------------------------
__global__ __launch_bounds__(256, 2)
void gemm1_kernel(const float* __restrict__ x,
                  const float* __restrict__ w1,
                  const float* __restrict__ w3) {
    __shared__ __half Xs [2][64][G1_XS];
    __shared__ __half W1s[2][64][G1_XS];
    __shared__ __half W3s[2][64][G1_XS];
    __shared__ int    toks[64];

    const int bx    = blockIdx.x;
    const int strip = bx & (NSTRIP - 1);
    const int ht    = (bx >> 2) % G1_NT_H;
    const int e     = bx / (NSTRIP * G1_NT_H);
    const int hb    = ht * 64;
    const int base  = g_off[e];
    const int nt    = g_off[e + 1] - base;

    const int tid  = threadIdx.x;
    const int lane = tid & 31;
    const int wid  = tid >> 5;
    const int wm   = wid & 1;       // 2 m-warps (32 rows each)
    const int wn   = wid >> 1;      // 4 n-warps (16 cols each)

    const float* w1e = w1 + ((size_t)e * kH + hb) * kD;
    const float* w3e = w3 + ((size_t)e * kH + hb) * kD;

    const int lrow = lane & 15;
    const int lcol = (lane >> 4) * 8;

    const int NST = kD / 32;   // 32

    for (int t0 = strip * 64; t0 < nt; t0 += NSTRIP * 64) {
        const int ntt = min(64, nt - t0);

        __syncthreads();
        if (tid < 64)
            toks[tid] = g_pairs[base + t0 + min(tid, ntt - 1)] / kTOPK;
        __syncthreads();

        float4 sx[2], s1[2], s3[2];
        auto ldg_stage = [&](int d0) {
            #pragma unroll
            for (int r = 0; r < 2; r++) {            // 64 x 32 fp32 each, 2/thread
                int c = tid + r * 256;
                int m = c >> 3, k4 = (c & 7) * 4;
                sx[r] = *(const float4*)&x  [(size_t)toks[m] * kD + d0 + k4];
                s1[r] = *(const float4*)&w1e[(size_t)m       * kD + d0 + k4];
                s3[r] = *(const float4*)&w3e[(size_t)m       * kD + d0 + k4];
            }
        };
        auto sts_stage = [&](int s) {
            #pragma unroll
            for (int r = 0; r < 2; r++) {
                int c = tid + r * 256;
                int m = c >> 3, k4 = (c & 7) * 4;
                *(uint2*)&Xs [s][m][k4] = cvt4(sx[r]);
                *(uint2*)&W1s[s][m][k4] = cvt4(s1[r]);
                *(uint2*)&W3s[s][m][k4] = cvt4(s3[r]);
            }
        };

        ldg_stage(0);
        sts_stage(0);
        __syncthreads();

        float acc1[2][2][4], acc3[2][2][4];
        #pragma unroll
        for (int mt = 0; mt < 2; mt++)
            #pragma unroll
            for (int j = 0; j < 2; j++)
                #pragma unroll
                for (int q = 0; q < 4; q++) { acc1[mt][j][q] = 0.f; acc3[mt][j][q] = 0.f; }

        for (int ks = 0; ks < NST; ks++) {
            int s = ks & 1;
            if (ks + 1 < NST) ldg_stage((ks + 1) * 32);

            #pragma unroll
            for (int kk = 0; kk < 2; kk++) {
                uint32_t a[2][4], b1[4], b3[4];
                #pragma unroll
                for (int mt = 0; mt < 2; mt++)
                    ldsm_x4(a[mt], s2u(&Xs[s][wm * 32 + mt * 16 + lrow][kk * 16 + lcol]));
                ldsm_x4(b1, s2u(&W1s[s][wn * 16 + lrow][kk * 16 + lcol]));
                ldsm_x4(b3, s2u(&W3s[s][wn * 16 + lrow][kk * 16 + lcol]));
                #pragma unroll
                for (int mt = 0; mt < 2; mt++)
                    #pragma unroll
                    for (int j = 0; j < 2; j++) {
                        mma16816(acc1[mt][j], a[mt], b1[j], b1[2 + j]);
                        mma16816(acc3[mt][j], a[mt], b3[j], b3[2 + j]);
                    }
            }

            if (ks + 1 < NST) sts_stage(s ^ 1);
            __syncthreads();
        }

        // epilogue: silu(h1)*h3 -> g_hbuf (fp16)
        #pragma unroll
        for (int mt = 0; mt < 2; mt++) {
            int row0 = wm * 32 + mt * 16 + (lane >> 2);
            #pragma unroll
            for (int j = 0; j < 2; j++) {
                int col = hb + wn * 16 + j * 8 + (lane & 3) * 2;
                if (row0 < ntt) {
                    float v0 = silu(acc1[mt][j][0]) * acc3[mt][j][0];
                    float v1 = silu(acc1[mt][j][1]) * acc3[mt][j][1];
                    *(__half2*)&g_hbuf[(size_t)(base + t0 + row0) * kH + col] =
                        __floats2half2_rn(v0, v1);
                }
                if (row0 + 8 < ntt) {
                    float v0 = silu(acc1[mt][j][2]) * acc3[mt][j][2];
                    float v1 = silu(acc1[mt][j][3]) * acc3[mt][j][3];
                    *(__half2*)&g_hbuf[(size_t)(base + t0 + row0 + 8) * kH + col] =
                        __floats2half2_rn(v0, v1);
                }
            }
        }
    }
}

// ---------------------------------------------------------------------------
// GEMM2. 256 threads, 8 warps: 4(m,16) x 2(n,32). 88 stages of k32.
// grid.x = 4 strips * 16 dtiles * 8 experts = 512.  3 CTAs/SM.
// Block tile: 64 tokens x 64 d.
// ---------------------------------------------------------------------------
__global__ __launch_bounds__(256, 3)
void gemm2_kernel(const float* __restrict__ w2, float* __restrict__ out) {
    __shared__ __half As[2][64][G2_AS];
    __shared__ __half Bs[2][32][G2_BS];
    __shared__ int    prs[64];

    const int bx    = blockIdx.x;
    const int strip = bx & (NSTRIP - 1);
    const int dt    = (bx >> 2) % G2_NT_D;
    const int e     = bx / (NSTRIP * G2_NT_D);
    const int ib    = dt * 64;
    const int base  = g_off[e];
    const int nt    = g_off[e + 1] - base;

    const int tid  = threadIdx.x;
    const int lane = tid & 31;
    const int wid  = tid >> 5;
    const int wm   = wid & 3;       // 4 m-warps (16 rows each)
    const int wn   = wid >> 2;      // 2 n-warps (32 cols each)

    const float* w2e = w2 + (size_t)e * kH * kD + ib;

    const int lrow = lane & 15;
    const int lcol = (lane >> 4) * 8;
    const int ti   = lane >> 3;
    const int trow = (ti >> 1) * 8 + (lane & 7);
    const int tcol = (ti & 1) * 8;

    const int NST = kH / 32;   // 88

    for (int t0 = strip * 64; t0 < nt; t0 += NSTRIP * 64) {
        const int ntt = min(64, nt - t0);

        __syncthreads();
        if (tid < 64)
            prs[tid] = g_pairs[base + t0 + min(tid, ntt - 1)];
        __syncthreads();

        uint4  stA;
        float4 stB[2];
        const int am = tid >> 2;              // A row 0..63
        const int ac = (tid & 3) * 8;         // A col (halves)
        auto ldg_stage = [&](int h0) {
            int arow = min(am, ntt - 1);
            stA = *(const uint4*)&g_hbuf[(size_t)(base + t0 + arow) * kH + h0 + ac];
            #pragma unroll
            for (int r = 0; r < 2; r++) {     // B: 32 x 64 fp32, 2/thread
                int i = tid + r * 256;
                int h = i >> 4, d4 = (i & 15) * 4;
                stB[r] = *(const float4*)&w2e[(size_t)(h0 + h) * kD + d4];
            }
        };
        auto sts_stage = [&](int s) {
            *(uint4*)&As[s][am][ac] = stA;
            #pragma unroll
            for (int r = 0; r < 2; r++) {
                int i = tid + r * 256;
                int h = i >> 4, d4 = (i & 15) * 4;
                *(uint2*)&Bs[s][h][d4] = cvt4(stB[r]);
            }
        };

        ldg_stage(0);
        sts_stage(0);
        __syncthreads();

        float acc[4][4];
        #pragma unroll
        for (int ntl = 0; ntl < 4; ntl++)
            #pragma unroll
            for (int q = 0; q < 4; q++) acc[ntl][q] = 0.f;

        for (int ks = 0; ks < NST; ks++) {
            int s = ks & 1;
            if (ks + 1 < NST) ldg_stage((ks + 1) * 32);

            #pragma unroll
            for (int kk = 0; kk < 2; kk++) {
                uint32_t a[4], b[2][4];
                ldsm_x4(a, s2u(&As[s][wm * 16 + lrow][kk * 16 + lcol]));
                #pragma unroll
                for (int g2 = 0; g2 < 2; g2++)
                    ldsm_x4_t(b[g2], s2u(&Bs[s][kk * 16 + trow][wn * 32 + g2 * 16 + tcol]));
                #pragma unroll
                for (int ntl = 0; ntl < 4; ntl++) {
                    int g2 = ntl >> 1, sub = ntl & 1;
                    mma16816(acc[ntl], a, b[g2][sub], b[g2][2 + sub]);
                }
            }

            if (ks + 1 < NST) sts_stage(s ^ 1);
            __syncthreads();
        }

        // epilogue: fp32 stores to out[pair][d]
        {
            int row0 = wm * 16 + (lane >> 2);
            #pragma unroll
            for (int ntl = 0; ntl < 4; ntl++) {
                int col = ib + wn * 32 + ntl * 8 + (lane & 3) * 2;
                if (row0 < ntt) {
                    float2 v = { acc[ntl][0], acc[ntl][1] };
                    *(float2*)&out[(size_t)prs[row0] * kD + col] = v;
                }
                if (row0 + 8 < ntt) {
                    float2 v = { acc[ntl][2], acc[ntl][3] };
                    *(float2*)&out[(size_t)prs[row0 + 8] * kD + col] = v;
                }
            }
        }
    }
}

// ---------------------------------------------------------------------------
extern "C" void kernel_launch(void* const* d_in, const int* in_sizes, int n_in,
                              void* d_out, int out_size) {
    const float* x    = (const float*)d_in[0];
    const void*  eidx = d_in[1];
    const float* w1   = (const float*)d_in[2];
    const float* w2   = (const float*)d_in[3];
    const float* w3   = (const float*)d_in[4];
    float*       out  = (float*)d_out;

    route_kernel<<<1, NP>>>(eidx);
    gemm1_kernel<<<NSTRIP * G1_NT_H * kE, 256>>>(x, w1, w3);
    gemm2_kernel<<<NSTRIP * G2_NT_D * kE, 256>>>(w2, out);
}

// round 16
// speedup vs baseline: 1.0389x; 1.0389x over previous
#include <cuda_runtime.h>
#include <cuda_fp16.h>
#include <cstdint>

// MoE SwiGLU via fp16 tensor cores (mma.m16n8k16, fp32 accum).
// R15 fix: SMEM_BYTES 41216 -> 41472 (toks[128] = 512B, not 256B).
// R14 design: single fused launch for gemm1+gemm2 with per-expert dataflow
// sync (g1 blocks release g_done[e]; g2 blocks acquire-spin until 88). Route
// kernel also resets counters -> replay-safe. Tile configs = R12 verbatim.
//   1) route_kernel : bucket pairs by expert + reset g_done
//   2) fused_kernel : bids 0..703 gemm1, bids 704..959 gemm2

namespace {
constexpr int kE = 8;
constexpr int kTOPK = 2;
constexpr int kH = 2816;
constexpr int kD = 1024;
constexpr int NP = 1024;

// GEMM1: BM=128 tokens, BN=64 h (x2 matrices), BK=32 (R12)
constexpr int G1_NT_H = kH / 64;        // 44 h-tiles
constexpr int G1_XS = 40;               // smem row stride fp16 (32+8 pad)
constexpr int G1_BLOCKS = 2 * G1_NT_H * kE;         // 704
constexpr int G1_PER_E  = 2 * G1_NT_H;              // 88
// GEMM2: BM=128 tokens, BN=64 d, BK=32 (R4/R12)
constexpr int G2_NT_D = kD / 64;        // 16 d-tiles
constexpr int G2_AS = 40;
constexpr int G2_BS = 72;
constexpr int G2_BLOCKS = 2 * G2_NT_D * kE;         // 256

// fused smem: gemm1 needs 20480 + 10240 + 10240 + 512 = 41472 bytes
constexpr int SMEM_BYTES = 41472;
}

__device__ int    g_off[kE + 1];
__device__ int    g_pairs[NP];
__device__ int    g_done[kE];
__device__ __half g_hbuf[(size_t)NP * kH];   // 5.77 MB fp16 intermediate

// ---------------------------------------------------------------------------
// helpers
// ---------------------------------------------------------------------------
__device__ __forceinline__ uint32_t s2u(const void* p) {
    return (uint32_t)__cvta_generic_to_shared(p);
}
__device__ __forceinline__ void ldsm_x4(uint32_t r[4], uint32_t addr) {
    asm volatile("ldmatrix.sync.aligned.m8n8.x4.shared.b16 {%0,%1,%2,%3}, [%4];"
                 : "=r"(r[0]), "=r"(r[1]), "=r"(r[2]), "=r"(r[3]) : "r"(addr));
}
__device__ __forceinline__ void ldsm_x4_t(uint32_t r[4], uint32_t addr) {
    asm volatile("ldmatrix.sync.aligned.m8n8.x4.trans.shared.b16 {%0,%1,%2,%3}, [%4];"
                 : "=r"(r[0]), "=r"(r[1]), "=r"(r[2]), "=r"(r[3]) : "r"(addr));
}
__device__ __forceinline__ void mma16816(float c[4], const uint32_t a[4],
                                         uint32_t b0, uint32_t b1) {
    asm volatile(
        "mma.sync.aligned.m16n8k16.row.col.f32.f16.f16.f32 "
        "{%0,%1,%2,%3},{%4,%5,%6,%7},{%8,%9},{%0,%1,%2,%3};"
        : "+f"(c[0]), "+f"(c[1]), "+f"(c[2]), "+f"(c[3])
        : "r"(a[0]), "r"(a[1]), "r"(a[2]), "r"(a[3]), "r"(b0), "r"(b1));
}
__device__ __forceinline__ uint32_t h2u(__half2 h) {
    return *reinterpret_cast<uint32_t*>(&h);
}
__device__ __forceinline__ uint2 cvt4(float4 v) {
    uint2 u = { h2u(__floats2half2_rn(v.x, v.y)),
                h2u(__floats2half2_rn(v.z, v.w)) };
    return u;
}
__device__ __forceinline__ float silu(float z) {
    return z / (1.0f + __expf(-z));
}

// ---------------------------------------------------------------------------
// Routing (int32/int64 dtype auto-detect; validated R3+) + counter reset.
// Runs as its own launch -> stream-serialized before the fused kernel, so
// g_done is reset for every graph replay with no flags/epochs.
// ---------------------------------------------------------------------------
__global__ void route_kernel(const void* __restrict__ eidx_raw) {
    __shared__ int cnt[kE];
    __shared__ int cur[kE];
    __shared__ int not64;
    int tid = threadIdx.x;
    if (tid < kE) { cnt[tid] = 0; g_done[tid] = 0; }
    if (tid == 0) not64 = 0;
    __syncthreads();

    const long long* p64 = (const long long*)eidx_raw;
    if (tid < NP / 2) {
        long long v = p64[tid];
        if (v < 0 || v >= kE) not64 = 1;
    }
    __syncthreads();

    int e = not64 ? ((const int*)eidx_raw)[tid] : (int)p64[tid];

    atomicAdd(&cnt[e], 1);
    __syncthreads();
    if (tid == 0) {
        int o = 0;
        for (int i = 0; i < kE; i++) { g_off[i] = o; cur[i] = o; o += cnt[i]; }
        g_off[kE] = o;
    }
    __syncthreads();
    int p = atomicAdd(&cur[e], 1);
    g_pairs[p] = tid;
}

// ---------------------------------------------------------------------------
// Fused kernel. bids [0, 704): gemm1 role (R12 verbatim body).
//               bids [704, 960): gemm2 role (R12/R4 verbatim body) after
//               acquiring g_done[e] == 88.
// Deadlock-free: blocks are placed in ascending-bid order; every block placed
// before any g2 block is a g1 block, and g1 blocks complete unconditionally.
// ---------------------------------------------------------------------------
__global__ __launch_bounds__(256, 2)
void fused_kernel(const float* __restrict__ x,
                  const float* __restrict__ w1,
                  const float* __restrict__ w3,
                  const float* __restrict__ w2,
                  float* __restrict__ out) {
    __shared__ __align__(16) char smem[SMEM_BYTES];

    const int tid  = threadIdx.x;
    const int lane = tid & 31;
    const int wid  = tid >> 5;

    if (blockIdx.x < G1_BLOCKS) {
        // ================= GEMM1 + SwiGLU (R12) =================
        // smem layout: Xs[2][128][40] | W1s[2][64][40] | W3s[2][64][40] | toks[128]
        typedef __half XsT [2][128][G1_XS];
        typedef __half WsT [2][64][G1_XS];
        XsT& Xs  = *reinterpret_cast<XsT*>(smem);
        WsT& W1s = *reinterpret_cast<WsT*>(smem + 20480);
        WsT& W3s = *reinterpret_cast<WsT*>(smem + 30720);
        int* toks = reinterpret_cast<int*>(smem + 40960);

        const int bx    = blockIdx.x;
        const int strip = bx & 1;
        const int ht    = (bx >> 1) % G1_NT_H;
        const int e     = bx / (2 * G1_NT_H);
        const int hb    = ht * 64;
        const int base  = g_off[e];
        const int nt    = g_off[e + 1] - base;

        const int wm = wid & 1;        // 2 m-warps (64 rows each)
        const int wn = wid >> 1;       // 4 n-warps (16 cols each)

        const float* w1e = w1 + ((size_t)e * kH + hb) * kD;
        const float* w3e = w3 + ((size_t)e * kH + hb) * kD;

        const int lrow = lane & 15;
        const int lcol = (lane >> 4) * 8;
        const int NST  = kD / 32;      // 32

        for (int t0 = strip * 128; t0 < nt; t0 += 256) {
            const int ntt = min(128, nt - t0);

            __syncthreads();
            if (tid < 128)
                toks[tid] = g_pairs[base + t0 + min(tid, ntt - 1)] / kTOPK;
            __syncthreads();

            float4 sx[4], s1[2], s3[2];
            auto ldg_stage = [&](int d0) {
                #pragma unroll
                for (int r = 0; r < 4; r++) {            // X: 128x32 fp32
                    int c = tid + r * 256;
                    int m = c >> 3, k4 = (c & 7) * 4;
                    sx[r] = *(const float4*)&x[(size_t)toks[m] * kD + d0 + k4];
                }
                #pragma unroll
                for (int r = 0; r < 2; r++) {            // W: 64x32 fp32 each
                    int c = tid + r * 256;
                    int n = c >> 3, k4 = (c & 7) * 4;
                    s1[r] = *(const float4*)&w1e[(size_t)n * kD + d0 + k4];
                    s3[r] = *(const float4*)&w3e[(size_t)n * kD + d0 + k4];
                }
            };
            auto sts_stage = [&](int s) {
                #pragma unroll
                for (int r = 0; r < 4; r++) {
                    int c = tid + r * 256;
                    int m = c >> 3, k4 = (c & 7) * 4;
                    *(uint2*)&Xs[s][m][k4] = cvt4(sx[r]);
                }
                #pragma unroll
                for (int r = 0; r < 2; r++) {
                    int c = tid + r * 256;
                    int n = c >> 3, k4 = (c & 7) * 4;
                    *(uint2*)&W1s[s][n][k4] = cvt4(s1[r]);
                    *(uint2*)&W3s[s][n][k4] = cvt4(s3[r]);
                }
            };

            ldg_stage(0);
            sts_stage(0);
            __syncthreads();

            float acc1[4][2][4], acc3[4][2][4];
            #pragma unroll
            for (int mt = 0; mt < 4; mt++)
                #pragma unroll
                for (int j = 0; j < 2; j++)
                    #pragma unroll
                    for (int q = 0; q < 4; q++) { acc1[mt][j][q] = 0.f; acc3[mt][j][q] = 0.f; }

            for (int ks = 0; ks < NST; ks++) {
                int s = ks & 1;
                if (ks + 1 < NST) ldg_stage((ks + 1) * 32);

                #pragma unroll
                for (int kk = 0; kk < 2; kk++) {
                    uint32_t a[4][4], b1[4], b3[4];
                    #pragma unroll
                    for (int mt = 0; mt < 4; mt++)
                        ldsm_x4(a[mt], s2u(&Xs[s][wm * 64 + mt * 16 + lrow][kk * 16 + lcol]));
                    ldsm_x4(b1, s2u(&W1s[s][wn * 16 + lrow][kk * 16 + lcol]));
                    ldsm_x4(b3, s2u(&W3s[s][wn * 16 + lrow][kk * 16 + lcol]));
                    #pragma unroll
                    for (int mt = 0; mt < 4; mt++)
                        #pragma unroll
                        for (int j = 0; j < 2; j++) {
                            mma16816(acc1[mt][j], a[mt], b1[j], b1[2 + j]);
                            mma16816(acc3[mt][j], a[mt], b3[j], b3[2 + j]);
                        }
                }

                if (ks + 1 < NST) sts_stage(s ^ 1);
                __syncthreads();
            }

            // epilogue: silu(h1)*h3 -> g_hbuf (fp16)
            #pragma unroll
            for (int mt = 0; mt < 4; mt++) {
                int row0 = wm * 64 + mt * 16 + (lane >> 2);
                #pragma unroll
                for (int j = 0; j < 2; j++) {
                    int col = hb + wn * 16 + j * 8 + (lane & 3) * 2;
                    if (row0 < ntt) {
                        float v0 = silu(acc1[mt][j][0]) * acc3[mt][j][0];
                        float v1 = silu(acc1[mt][j][1]) * acc3[mt][j][1];
                        *(__half2*)&g_hbuf[(size_t)(base + t0 + row0) * kH + col] =
                            __floats2half2_rn(v0, v1);
                    }
                    if (row0 + 8 < ntt) {
                        float v0 = silu(acc1[mt][j][2]) * acc3[mt][j][2];
                        float v1 = silu(acc1[mt][j][3]) * acc3[mt][j][3];
                        *(__half2*)&g_hbuf[(size_t)(base + t0 + row0 + 8) * kH + col] =
                            __floats2half2_rn(v0, v1);
                    }
                }
            }
        }

        // release: all stores visible, then count this block done for expert e
        __threadfence();
        __syncthreads();
        if (tid == 0) atomicAdd(&g_done[e], 1);

    } else {
        // ================= GEMM2 (R12/R4) =================
        // smem layout: As[2][128][40] | Bs[2][32][72] | prs[128]
        typedef __half AsT [2][128][G2_AS];
        typedef __half BsT [2][32][G2_BS];
        AsT& As = *reinterpret_cast<AsT*>(smem);
        BsT& Bs = *reinterpret_cast<BsT*>(smem + 20480);
        int* prs = reinterpret_cast<int*>(smem + 29696);

        const int bx    = blockIdx.x - G1_BLOCKS;
        const int strip = bx & 1;
        const int dt    = (bx >> 1) % G2_NT_D;
        const int e     = bx / (2 * G2_NT_D);
        const int ib    = dt * 64;

        // acquire: wait until all 88 gemm1 blocks of expert e have released
        if (tid == 0) {
            while (*(volatile int*)&g_done[e] < G1_PER_E) __nanosleep(128);
        }
        __syncthreads();
        __threadfence();

        const int base = g_off[e];
        const int nt   = g_off[e + 1] - base;

        const int wm = wid & 3;        // 4 m-warps (32 rows)
        const int wn = wid >> 2;       // 2 n-warps (32 cols)

        const float* w2e = w2 + (size_t)e * kH * kD + ib;

        const int lrow = lane & 15;
        const int lcol = (lane >> 4) * 8;
        const int ti   = lane >> 3;
        const int trow = (ti >> 1) * 8 + (lane & 7);
        const int tcol = (ti & 1) * 8;

        for (int t0 = strip * 128; t0 < nt; t0 += 256) {
            const int ntt = min(128, nt - t0);

            __syncthreads();
            if (tid < 128)
                prs[tid] = g_pairs[base + t0 + min(tid, ntt - 1)];
            __syncthreads();

            uint4  stA[2];
            float4 stB[2];
            auto ldg_stage = [&](int h0) {
                #pragma unroll
                for (int r = 0; r < 2; r++) {
                    int i = tid + r * 256;
                    int m = i >> 2, c8 = i & 3;
                    int tc = min(m, ntt - 1);
                    stA[r] = *(const uint4*)&g_hbuf[(size_t)(base + t0 + tc) * kH + h0 + c8 * 8];
                    int h = i >> 4, d4 = i & 15;
                    stB[r] = *(const float4*)&w2e[(size_t)(h0 + h) * kD + d4 * 4];
                }
            };
            auto sts_stage = [&](int s) {
                #pragma unroll
                for (int r = 0; r < 2; r++) {
                    int i = tid + r * 256;
                    int m = i >> 2, c8 = i & 3;
                    *(uint4*)&As[s][m][c8 * 8] = stA[r];
                    int h = i >> 4, d4 = i & 15;
                    float4 v = stB[r];
                    uint2 u = { h2u(__floats2half2_rn(v.x, v.y)),
                                h2u(__floats2half2_rn(v.z, v.w)) };
                    *(uint2*)&Bs[s][h][d4 * 4] = u;
                }
            };

            ldg_stage(0);
            sts_stage(0);
            __syncthreads();

            float acc[2][4][4];
            #pragma unroll
            for (int mt = 0; mt < 2; mt++)
                #pragma unroll
                for (int ntl = 0; ntl < 4; ntl++)
                    #pragma unroll
                    for (int q = 0; q < 4; q++) acc[mt][ntl][q] = 0.f;

            const int NST = kH / 32;   // 88
            for (int ks = 0; ks < NST; ks++) {
                int s = ks & 1;
                if (ks + 1 < NST) ldg_stage((ks + 1) * 32);

                #pragma unroll
                for (int kk = 0; kk < 2; kk++) {
                    uint32_t a[2][4], b[2][4];
                    #pragma unroll
                    for (int mt = 0; mt < 2; mt++)
                        ldsm_x4(a[mt], s2u(&As[s][wm * 32 + mt * 16 + lrow][kk * 16 + lcol]));
                    #pragma unroll
                    for (int g2i = 0; g2i < 2; g2i++)
                        ldsm_x4_t(b[g2i], s2u(&Bs[s][kk * 16 + trow][wn * 32 + g2i * 16 + tcol]));
                    #pragma unroll
                    for (int mt = 0; mt < 2; mt++)
                        #pragma unroll
                        for (int ntl = 0; ntl < 4; ntl++) {
                            int g2i = ntl >> 1, sub = ntl & 1;
                            mma16816(acc[mt][ntl], a[mt], b[g2i][sub], b[g2i][2 + sub]);
                        }
                }

                if (ks + 1 < NST) sts_stage(s ^ 1);
                __syncthreads();
            }

            #pragma unroll
            for (int mt = 0; mt < 2; mt++) {
                int row0 = wm * 32 + mt * 16 + (lane >> 2);
                #pragma unroll
                for (int ntl = 0; ntl < 4; ntl++) {
                    int col = ib + wn * 32 + ntl * 8 + (lane & 3) * 2;
                    if (row0 < ntt) {
                        float2 v = { acc[mt][ntl][0], acc[mt][ntl][1] };
                        *(float2*)&out[(size_t)prs[row0] * kD + col] = v;
                    }
                    if (row0 + 8 < ntt) {
                        float2 v = { acc[mt][ntl][2], acc[mt][ntl][3] };
                        *(float2*)&out[(size_t)prs[row0 + 8] * kD + col] = v;
                    }
                }
            }
        }
    }
}

// ---------------------------------------------------------------------------
extern "C" void kernel_launch(void* const* d_in, const int* in_sizes, int n_in,
                              void* d_out, int out_size) {
    const float* x    = (const float*)d_in[0];
    const void*  eidx = d_in[1];
    const float* w1   = (const float*)d_in[2];
    const float* w2   = (const float*)d_in[3];
    const float* w3   = (const float*)d_in[4];
    float*       out  = (float*)d_out;

    route_kernel<<<1, NP>>>(eidx);
    fused_kernel<<<G1_BLOCKS + G2_BLOCKS, 256>>>(x, w1, w3, w2, out);
}